// round 8
// baseline (speedup 1.0000x reference)
#include <cuda_runtime.h>

#define NL     32
#define NF     720
#define NSUB   60
#define DTF    60.0f
#define SCALE  256.0f      // Sturm prescale: work with 256*(symmetrized DT*L)
#define CL     23          // modal chunk length
#define NCH    32          // 31 full chunks of 23 + last of 6  (31*23+6 = 719)

typedef unsigned long long u64;
#define FULL 0xffffffffu

// Persistent scratch (__device__ globals per allocation rules)
__device__ float  g_A  [NL * NL];   // A[l*32+r] = Q[r][l] / d_r   (w = A z)
__device__ float2 g_Lam[NL];        // per-mode outer-step multiplier  Lambda_l
__device__ float2 g_G0 [NL];        // per-mode forcing coeff (tau_k)
__device__ float2 g_G1 [NL];        // per-mode forcing coeff (tau_{k+1})
__device__ float2 g_Z  [NF * NL];   // modal states z_k, k = 1..719

// ---- packed f32x2 helpers ---------------------------------------------------
__device__ __forceinline__ u64 pk2(float lo, float hi) {
    u64 r; asm("mov.b64 %0, {%1, %2};" : "=l"(r) : "f"(lo), "f"(hi)); return r;
}
__device__ __forceinline__ void upk2(float& lo, float& hi, u64 v) {
    asm("mov.b64 {%0, %1}, %2;" : "=f"(lo), "=f"(hi) : "l"(v));
}
__device__ __forceinline__ void ffma2(u64& d, u64 a, u64 b) {
    asm("fma.rn.f32x2 %0, %1, %2, %3;" : "=l"(d) : "l"(a), "l"(b), "l"(d));
}

// Sturm count: # eigenvalues of scaled symmetric tridiag (ch diag, s2h off^2) < x
__device__ __forceinline__ int sturm_count(float x,
                                           const float* __restrict__ ch,
                                           const float* __restrict__ s2h)
{
    float p0 = 1.0f;
    float p1 = ch[0] - x;
    bool  s1 = (p1 < 0.0f) || (p1 == 0.0f);
    int   cnt = s1 ? 1 : 0;
    #pragma unroll
    for (int r = 1; r < NL; ++r) {
        float p2 = fmaf(ch[r] - x, p1, -s2h[r] * p0);
        bool sg = (p2 < 0.0f);
        if (p2 == 0.0f) sg = !s1;
        cnt += (sg != s1) ? 1 : 0;
        float ap = fabsf(p2);
        float sc = 1.0f;
        if (ap > 1e18f) sc = 1e-18f;
        else if (ap < 1e-18f) sc = 1e18f;
        p0 = p1 * sc;
        p1 = p2 * sc;
        s1 = sg;
    }
    return cnt;
}

// ---------------------------------------------------------------------------
// Kernel 1: eigen solve. 32 blocks x 1 warp. Block l finds eigenpair #l of the
// symmetrized substep generator, then the per-mode outer-step constants.
// ---------------------------------------------------------------------------
__global__ void __launch_bounds__(32, 1)
eigen_kernel(const float* __restrict__ pk, const float* __restrict__ fc)
{
    __shared__ float ch [NL];       // scaled diag of sym(DT*L)
    __shared__ float sh [NL + 1];   // scaled off-diag, sh[0]=sh[32]=0
    __shared__ float s2h[NL];       // sh^2
    __shared__ float dinv[NL];      // 1/d_r  (symmetrizer)
    __shared__ float dp[NL], wk[NL], vv[NL], vb[NL];

    const int lane = threadIdx.x;
    const int l    = blockIdx.x;                 // eigen index (0 = smallest)

    const float kin  = expf(pk[2 * lane]);
    const float kout = expf(pk[2 * lane + 1]);

    // d_r = exp( sum_{j=1..r} 0.5*(pk[2j-1] - pk[2j]) )  (d_0 = 1)
    float t = (lane > 0) ? 0.5f * (pk[2 * lane - 1] - pk[2 * lane]) : 0.0f;
    #pragma unroll
    for (int o = 1; o < 32; o <<= 1) {
        float u = __shfl_up_sync(FULL, t, o);
        if (lane >= o) t += u;
    }
    dinv[lane] = expf(-t);

    // scaled symmetric tridiagonal: C = SCALE * sym(DT*L)
    const float c = -DTF * (((lane > 0) ? kin : 0.0f) + kout) * SCALE;
    const float s = (lane > 0)
        ? DTF * expf(0.5f * (pk[2 * lane] + pk[2 * lane - 1])) * SCALE
        : 0.0f;
    ch[lane]  = c;
    sh[lane]  = s;
    s2h[lane] = s * s;
    if (lane == 0) sh[NL] = 0.0f;
    __syncwarp();

    // Gershgorin interval
    float rad = sh[lane] + sh[lane + 1];
    float lo  = c - rad, hi = c + rad;
    #pragma unroll
    for (int o = 16; o > 0; o >>= 1) {
        lo = fminf(lo, __shfl_xor_sync(FULL, lo, o));
        hi = fmaxf(hi, __shfl_xor_sync(FULL, hi, o));
    }
    float width = hi - lo;
    float a_ = lo - 1e-6f * (fabsf(width) + 1.0f);
    float b_ = hi + 1e-6f * (fabsf(width) + 1.0f);

    // 32-point parallel bisection, 6 rounds (interval /33 per round)
    for (int round = 0; round < 6; ++round) {
        float x = a_ + (b_ - a_) * (float)(lane + 1) * (1.0f / 33.0f);
        int cnt = sturm_count(x, ch, s2h);
        unsigned mask = __ballot_sync(FULL, cnt <= l);
        if (mask) {
            int j = 31 - __clz((int)mask);               // highest lane with cnt<=l
            float na = __shfl_sync(FULL, x, j);
            float nb = (j < 31) ? __shfl_sync(FULL, x, j + 1) : b_;
            a_ = na; b_ = nb;
        } else {
            b_ = __shfl_sync(FULL, x, 0);
        }
    }
    const float xhat = 0.5f * (a_ + b_);                 // scaled eigenvalue

    // Eigenvector: 3 rounds of inverse iteration (Thomas solve), lane 0 serial
    if (lane == 0) {
        for (int r = 0; r < NL; ++r) vb[r] = 1.0f;
        for (int it = 0; it < 3; ++it) {
            float dd = ch[0] - xhat;
            if (fabsf(dd) < 1e-12f) dd = (dd < 0.0f) ? -1e-12f : 1e-12f;
            dp[0] = dd; wk[0] = vb[0];
            for (int r = 1; r < NL; ++r) {
                float m = __fdividef(sh[r], dp[r - 1]);
                dd = (ch[r] - xhat) - m * sh[r];
                if (fabsf(dd) < 1e-12f) dd = (dd < 0.0f) ? -1e-12f : 1e-12f;
                dp[r] = dd;
                wk[r] = vb[r] - m * wk[r - 1];
            }
            vv[NL - 1] = __fdividef(wk[NL - 1], dp[NL - 1]);
            for (int r = NL - 2; r >= 0; --r)
                vv[r] = __fdividef(wk[r] - sh[r + 1] * vv[r + 1], dp[r]);
            float n2 = 0.0f;
            for (int r = 0; r < NL; ++r) n2 += vv[r] * vv[r];
            float inv = rsqrtf(n2);
            for (int r = 0; r < NL; ++r) vb[r] = vv[r] * inv;
        }
    }
    __syncwarp();

    // A column l: A[r][l] = Q[r][l] / d_r
    g_A[l * NL + lane] = vb[lane] * dinv[lane];

    // Per-mode constants in fp64 (cheap: O(100) fp64 ops on one lane)
    if (lane == 0) {
        const double mu = (double)xhat / (double)SCALE;  // eigenvalue of sym(DT*L)
        const double br = 1.0 + mu;                      // Re(beta): substep multiplier
        const double bi = -(double)DTF * (double)fc[0];  // Im(beta)

        // Lambda = beta^60 by squaring
        double xr = 1.0, xi = 0.0, prr = br, pii = bi;
        int e = NSUB;
        while (e) {
            if (e & 1) { double tr = xr * prr - xi * pii; xi = xr * pii + xi * prr; xr = tr; }
            double t2 = prr * prr - pii * pii; pii = 2.0 * prr * pii; prr = t2;
            e >>= 1;
        }

        // gamma sums: sum_j (1-j/60)*beta^(59-j) and sum_j (j/60)*beta^(59-j)
        double g0r = 0.0, g0i = 0.0, g1r = 0.0, g1i = 0.0;
        double pwr = 1.0, pwi = 0.0;
        for (int j = NSUB - 1; j >= 0; --j) {
            double w2 = (double)j / (double)NSUB;
            double w1 = 1.0 - w2;
            g0r += w1 * pwr; g0i += w1 * pwi;
            g1r += w2 * pwr; g1i += w2 * pwi;
            double tr = pwr * br - pwi * bi;
            pwi = pwr * bi + pwi * br;
            pwr = tr;
        }
        const double sc = (double)DTF * exp((double)pk[0]) * (double)vb[0];
        g_Lam[l] = make_float2((float)xr, (float)xi);
        g_G0[l]  = make_float2((float)(sc * g0r), (float)(sc * g0i));
        g_G1[l]  = make_float2((float)(sc * g1r), (float)(sc * g1i));
    }
}

// complex fp32 multiply
__device__ __forceinline__ float2 cmulf(float2 a, float2 b) {
    return make_float2(a.x * b.x - a.y * b.y, a.x * b.y + a.y * b.x);
}

// ---------------------------------------------------------------------------
// Kernel 2: modal evolution. ONE block, 32 warps. Warp c = chunk c, lane = mode.
// z_{k+1} = Lam*z_k + G0*tau_k + G1*tau_{k+1};  chunked scan, depth 23+31+23.
// ---------------------------------------------------------------------------
__global__ void __launch_bounds__(1024, 1)
modal_kernel(const float* __restrict__ TAx, const float* __restrict__ TAy)
{
    __shared__ float2 zloc[NCH][NL];
    __shared__ float2 carr[NCH][NL];

    const int l = threadIdx.x & 31;
    const int c = threadIdx.x >> 5;

    const float2 L  = g_Lam[l];
    const float2 G0 = g_G0[l];
    const float2 G1 = g_G1[l];

    const int k0  = c * CL;
    const int len = min(CL, (NF - 1) - k0);      // 23 for c<31, 6 for c=31

    float zr = 0.0f, zi = 0.0f;
    for (int m = 0; m < len; ++m) {
        const int k = k0 + m;
        float txa = TAx[k],     tya = TAy[k];
        float txb = TAx[k + 1], tyb = TAy[k + 1];
        float fr = txa * G0.x - tya * G0.y + txb * G1.x - tyb * G1.y;
        float fi = txa * G0.y + tya * G0.x + txb * G1.y + tyb * G1.x;
        float nr = fr + L.x * zr - L.y * zi;
        float ni = fi + L.x * zi + L.y * zr;
        zr = nr; zi = ni;
    }
    zloc[c][l] = make_float2(zr, zi);
    __syncthreads();

    if (c == 0) {
        // Lam^CL per lane
        float2 base = L, pw = make_float2(1.0f, 0.0f);
        int e = CL;
        while (e) { if (e & 1) pw = cmulf(pw, base); base = cmulf(base, base); e >>= 1; }

        float kr = 0.0f, ki = 0.0f;
        carr[0][l] = make_float2(0.0f, 0.0f);
        for (int cc = 0; cc < NCH - 1; ++cc) {
            float2 s = zloc[cc][l];
            float nr = pw.x * kr - pw.y * ki + s.x;
            float ni = pw.x * ki + pw.y * kr + s.y;
            kr = nr; ki = ni;
            carr[cc + 1][l] = make_float2(kr, ki);
        }
    }
    __syncthreads();

    float2 K = carr[c][l];
    zr = K.x; zi = K.y;
    for (int m = 0; m < len; ++m) {
        const int k = k0 + m;
        float txa = TAx[k],     tya = TAy[k];
        float txb = TAx[k + 1], tyb = TAy[k + 1];
        float fr = txa * G0.x - tya * G0.y + txb * G1.x - tyb * G1.y;
        float fi = txa * G0.y + tya * G0.x + txb * G1.y + tyb * G1.x;
        float nr = fr + L.x * zr - L.y * zi;
        float ni = fi + L.x * zi + L.y * zr;
        zr = nr; zi = ni;
        g_Z[(k + 1) * NL + l] = make_float2(zr, zi);
    }
}

// ---------------------------------------------------------------------------
// Kernel 3: output transform. U[k] = A*Re(z_k), V[k] = A*Im(z_k).
// 45 blocks x 512 threads; thread = (k within 16-tile, row r). FFMA2 inner loop.
// ---------------------------------------------------------------------------
__global__ void __launch_bounds__(512, 1)
transform_kernel(float* __restrict__ out)
{
    __shared__ float  As[NL * NL];
    __shared__ float2 Zs[16 * NL];

    const int tid = threadIdx.x;
    for (int i = tid; i < NL * NL; i += 512) As[i] = g_A[i];

    const int kbase = blockIdx.x * 16;
    for (int i = tid; i < 16 * NL; i += 512) {
        int kk = i >> 5, li = i & 31;
        int k = kbase + kk;
        Zs[i] = (k >= 1 && k < NF) ? g_Z[k * NL + li] : make_float2(0.0f, 0.0f);
    }
    __syncthreads();

    const int kk = tid >> 5, r = tid & 31;
    const int k  = kbase + kk;
    if (k >= NF) return;

    const u64* zv = reinterpret_cast<const u64*>(&Zs[kk * NL]);
    u64 acc = 0ull;
    #pragma unroll
    for (int li = 0; li < NL; ++li) {
        float a = As[li * NL + r];
        ffma2(acc, pk2(a, a), zv[li]);
    }
    float u, v;
    upk2(u, v, acc);
    out[k * NL + r]           = u;   // U[k][r]  (k=0 -> zeros via Zs guard)
    out[NF * NL + k * NL + r] = v;   // V[k][r]
}

extern "C" void kernel_launch(void* const* d_in, const int* in_sizes, int n_in,
                              void* d_out, int out_size)
{
    const float* pk  = (const float*)d_in[0];
    const float* TAx = (const float*)d_in[1];
    const float* TAy = (const float*)d_in[2];
    const float* fc  = (const float*)d_in[3];
    float* out = (float*)d_out;

    eigen_kernel    <<<NL, 32>>>(pk, fc);
    modal_kernel    <<<1, 1024>>>(TAx, TAy);
    transform_kernel<<<45, 512>>>(out);
}

// round 10
// speedup vs baseline: 2.2614x; 2.2614x over previous
#include <cuda_runtime.h>

#define NL     32
#define NF     720
#define NSUB   60
#define DTF    60.0f
#define SCALE  256.0f
#define CL     23
#define NCH    32          // 31 full chunks of 23 + last of 6 (31*23+6 = 719)

typedef unsigned long long u64;
#define FULL 0xffffffffu

// Persistent scratch
__device__ float  g_A  [NL * NL];   // A[l*32+r] = Q[r][l] / d_r   (w = A z)
__device__ float2 g_Lam[NL];
__device__ float2 g_G0 [NL];
__device__ float2 g_G1 [NL];
__device__ float2 g_Z  [NF * NL];

// ---- packed f32x2 helpers ---------------------------------------------------
__device__ __forceinline__ u64 pk2(float lo, float hi) {
    u64 r; asm("mov.b64 %0, {%1, %2};" : "=l"(r) : "f"(lo), "f"(hi)); return r;
}
__device__ __forceinline__ void upk2(float& lo, float& hi, u64 v) {
    asm("mov.b64 {%0, %1}, %2;" : "=f"(lo), "=f"(hi) : "l"(v));
}
__device__ __forceinline__ void ffma2(u64& d, u64 a, u64 b) {
    asm("fma.rn.f32x2 %0, %1, %2, %3;" : "=l"(d) : "l"(a), "l"(b), "l"(d));
}

// Sturm count: # eigenvalues of scaled symmetric tridiag < x
__device__ __forceinline__ int sturm_count(float x,
                                           const float* __restrict__ ch,
                                           const float* __restrict__ s2h)
{
    float p0 = 1.0f;
    float p1 = ch[0] - x;
    bool  s1 = (p1 < 0.0f) || (p1 == 0.0f);
    int   cnt = s1 ? 1 : 0;
    #pragma unroll
    for (int r = 1; r < NL; ++r) {
        float p2 = fmaf(ch[r] - x, p1, -s2h[r] * p0);
        bool sg = (p2 < 0.0f);
        if (p2 == 0.0f) sg = !s1;
        cnt += (sg != s1) ? 1 : 0;
        float ap = fabsf(p2);
        float sc = 1.0f;
        if (ap > 1e18f) sc = 1e-18f;
        else if (ap < 1e-18f) sc = 1e18f;
        p0 = p1 * sc;
        p1 = p2 * sc;
        s1 = sg;
    }
    return cnt;
}

__device__ __forceinline__ void cdmul(double& zr, double& zi, double ar, double ai) {
    double tr = zr * ar - zi * ai;
    zi = zr * ai + zi * ar;
    zr = tr;
}

// ---------------------------------------------------------------------------
// Kernel 1: eigen solve. 32 blocks x 1 warp.
// Bisection (lane-parallel) + Thomas inverse iteration (lane-0, REGISTERS)
// + fp64 constants tail (lane-parallel).
// ---------------------------------------------------------------------------
__global__ void __launch_bounds__(32, 1)
eigen_kernel(const float* __restrict__ pk, const float* __restrict__ fc)
{
    __shared__ float ch [NL];
    __shared__ float sh [NL];       // off-diag connecting (l-1, l); sh[0]=0
    __shared__ float s2h[NL];
    __shared__ float vsm[NL];

    const int lane = threadIdx.x;
    const int l    = blockIdx.x;

    const float kin  = expf(pk[2 * lane]);
    const float kout = expf(pk[2 * lane + 1]);

    // symmetrizer: dinv_r = exp(-sum_{j<=r} 0.5*(pk[2j-1]-pk[2j]))
    float t = (lane > 0) ? 0.5f * (pk[2 * lane - 1] - pk[2 * lane]) : 0.0f;
    #pragma unroll
    for (int o = 1; o < 32; o <<= 1) {
        float u = __shfl_up_sync(FULL, t, o);
        if (lane >= o) t += u;
    }
    const float dinv = expf(-t);

    // scaled symmetric tridiagonal
    const float c = -DTF * (((lane > 0) ? kin : 0.0f) + kout) * SCALE;
    const float s = (lane > 0)
        ? DTF * expf(0.5f * (pk[2 * lane] + pk[2 * lane - 1])) * SCALE
        : 0.0f;
    ch[lane]  = c;
    sh[lane]  = s;
    s2h[lane] = s * s;
    const float s_up = __shfl_down_sync(FULL, s, 1);
    const float offp = (lane < NL - 1) ? s_up : 0.0f;
    __syncwarp();

    // Gershgorin interval
    float rad = s + offp;
    float lo  = c - rad, hi = c + rad;
    #pragma unroll
    for (int o = 16; o > 0; o >>= 1) {
        lo = fminf(lo, __shfl_xor_sync(FULL, lo, o));
        hi = fmaxf(hi, __shfl_xor_sync(FULL, hi, o));
    }
    float width = hi - lo;
    float a_ = lo - 1e-6f * (fabsf(width) + 1.0f);
    float b_ = hi + 1e-6f * (fabsf(width) + 1.0f);

    // 32-point parallel bisection, 6 rounds
    for (int round = 0; round < 6; ++round) {
        float x = a_ + (b_ - a_) * (float)(lane + 1) * (1.0f / 33.0f);
        int cnt = sturm_count(x, ch, s2h);
        unsigned mask = __ballot_sync(FULL, cnt <= l);
        if (mask) {
            int j = 31 - __clz((int)mask);
            float na = __shfl_sync(FULL, x, j);
            float nb = (j < 31) ? __shfl_sync(FULL, x, j + 1) : b_;
            a_ = na; b_ = nb;
        } else {
            b_ = __shfl_sync(FULL, x, 0);
        }
    }
    const float xhat = 0.5f * (a_ + b_);

    // ---- Thomas inverse iteration, lane 0, all-register (R8 numerics) ----
    if (lane == 0) {
        float vb[NL];
        #pragma unroll
        for (int r = 0; r < NL; ++r) vb[r] = 1.0f;

        #pragma unroll
        for (int it = 0; it < 3; ++it) {
            float rp[NL], wk[NL];
            float dd = ch[0] - xhat;
            if (fabsf(dd) < 1e-12f) dd = (dd < 0.0f) ? -1e-12f : 1e-12f;
            rp[0] = __frcp_rn(dd);
            wk[0] = vb[0];
            #pragma unroll
            for (int r = 1; r < NL; ++r) {
                float sv = sh[r];
                float m  = sv * rp[r - 1];
                dd = (ch[r] - xhat) - m * sv;
                if (fabsf(dd) < 1e-12f) dd = (dd < 0.0f) ? -1e-12f : 1e-12f;
                rp[r] = __frcp_rn(dd);
                wk[r] = vb[r] - m * wk[r - 1];
            }
            // back-substitute in place (wk becomes the solution)
            wk[NL - 1] = wk[NL - 1] * rp[NL - 1];
            #pragma unroll
            for (int r = NL - 2; r >= 0; --r)
                wk[r] = (wk[r] - sh[r + 1] * wk[r + 1]) * rp[r];

            float n2 = 0.0f;
            #pragma unroll
            for (int r = 0; r < NL; ++r) n2 += wk[r] * wk[r];
            float inv = rsqrtf(n2);
            #pragma unroll
            for (int r = 0; r < NL; ++r) vb[r] = wk[r] * inv;
        }
        #pragma unroll
        for (int r = 0; r < NL; ++r) vsm[r] = vb[r];
    }
    __syncwarp();

    const float v  = vsm[lane];
    g_A[l * NL + lane] = v * dinv;
    const float v0 = vsm[0];

    // ---- lane-parallel fp64 tail (verified against R8 serial) ----
    const double mu = (double)xhat / (double)SCALE;
    const double br = 1.0 + mu;
    const double bi = -(double)DTF * (double)fc[0];

    double sqr_r[6], sqr_i[6];
    sqr_r[0] = br; sqr_i[0] = bi;
    #pragma unroll
    for (int k = 1; k < 6; ++k) {
        double rr = sqr_r[k-1], ii = sqr_i[k-1];
        sqr_r[k] = rr * rr - ii * ii;
        sqr_i[k] = 2.0 * rr * ii;
    }

    // per-lane powers: p1 = beta^(59-lane); p2 = beta^(27-lane) for lane<=27
    int e1 = 59 - lane;
    int e2 = 27 - lane;
    double p1r = 1.0, p1i = 0.0, p2r = 1.0, p2i = 0.0;
    #pragma unroll
    for (int k = 0; k < 6; ++k) {
        if (e1 & (1 << k)) cdmul(p1r, p1i, sqr_r[k], sqr_i[k]);
        if (e2 >= 0 && (e2 & (1 << k))) cdmul(p2r, p2i, sqr_r[k], sqr_i[k]);
    }

    // term t: weights (1-t/60, t/60) on beta^(59-t); t = lane and lane+32
    double w2a = (double)lane * (1.0 / 60.0),        w1a = 1.0 - w2a;
    double w2b = (double)(lane + 32) * (1.0 / 60.0), w1b = 1.0 - w2b;
    bool   hb  = (e2 >= 0);
    double g0r = w1a * p1r + (hb ? w1b * p2r : 0.0);
    double g0i = w1a * p1i + (hb ? w1b * p2i : 0.0);
    double g1r = w2a * p1r + (hb ? w2b * p2r : 0.0);
    double g1i = w2a * p1i + (hb ? w2b * p2i : 0.0);
    #pragma unroll
    for (int o = 16; o > 0; o >>= 1) {
        g0r += __shfl_xor_sync(FULL, g0r, o);
        g0i += __shfl_xor_sync(FULL, g0i, o);
        g1r += __shfl_xor_sync(FULL, g1r, o);
        g1i += __shfl_xor_sync(FULL, g1i, o);
    }

    if (lane == 0) {
        // Lambda = beta^60 = beta^32 * beta^16 * beta^8 * beta^4
        double Lr = sqr_r[5], Li = sqr_i[5];
        cdmul(Lr, Li, sqr_r[4], sqr_i[4]);
        cdmul(Lr, Li, sqr_r[3], sqr_i[3]);
        cdmul(Lr, Li, sqr_r[2], sqr_i[2]);
        const double sc = (double)DTF * (double)expf(pk[0]) * (double)v0;
        g_Lam[l] = make_float2((float)Lr, (float)Li);
        g_G0[l]  = make_float2((float)(sc * g0r), (float)(sc * g0i));
        g_G1[l]  = make_float2((float)(sc * g1r), (float)(sc * g1i));
    }
}

__device__ __forceinline__ float2 cmulf(float2 a, float2 b) {
    return make_float2(a.x * b.x - a.y * b.y, a.x * b.y + a.y * b.x);
}

// ---------------------------------------------------------------------------
// Kernel 2: modal evolution. ONE block, 32 warps. Warp c = chunk c, lane = mode.
// ---------------------------------------------------------------------------
__global__ void __launch_bounds__(1024, 1)
modal_kernel(const float* __restrict__ TAx, const float* __restrict__ TAy)
{
    __shared__ float2 zloc[NCH][NL];
    __shared__ float2 carr[NCH][NL];

    const int l = threadIdx.x & 31;
    const int c = threadIdx.x >> 5;

    const float2 L  = g_Lam[l];
    const float2 G0 = g_G0[l];
    const float2 G1 = g_G1[l];

    const int k0  = c * CL;
    const int len = min(CL, (NF - 1) - k0);

    float zr = 0.0f, zi = 0.0f;
    for (int m = 0; m < len; ++m) {
        const int k = k0 + m;
        float txa = TAx[k],     tya = TAy[k];
        float txb = TAx[k + 1], tyb = TAy[k + 1];
        float fr = txa * G0.x - tya * G0.y + txb * G1.x - tyb * G1.y;
        float fi = txa * G0.y + tya * G0.x + txb * G1.y + tyb * G1.x;
        float nr = fr + L.x * zr - L.y * zi;
        float ni = fi + L.x * zi + L.y * zr;
        zr = nr; zi = ni;
    }
    zloc[c][l] = make_float2(zr, zi);
    __syncthreads();

    if (c == 0) {
        float2 base = L, pw = make_float2(1.0f, 0.0f);
        int e = CL;
        while (e) { if (e & 1) pw = cmulf(pw, base); base = cmulf(base, base); e >>= 1; }

        float kr = 0.0f, ki = 0.0f;
        carr[0][l] = make_float2(0.0f, 0.0f);
        for (int cc = 0; cc < NCH - 1; ++cc) {
            float2 sv = zloc[cc][l];
            float nr = pw.x * kr - pw.y * ki + sv.x;
            float ni = pw.x * ki + pw.y * kr + sv.y;
            kr = nr; ki = ni;
            carr[cc + 1][l] = make_float2(kr, ki);
        }
    }
    __syncthreads();

    float2 K = carr[c][l];
    zr = K.x; zi = K.y;
    for (int m = 0; m < len; ++m) {
        const int k = k0 + m;
        float txa = TAx[k],     tya = TAy[k];
        float txb = TAx[k + 1], tyb = TAy[k + 1];
        float fr = txa * G0.x - tya * G0.y + txb * G1.x - tyb * G1.y;
        float fi = txa * G0.y + tya * G0.x + txb * G1.y + tyb * G1.x;
        float nr = fr + L.x * zr - L.y * zi;
        float ni = fi + L.x * zi + L.y * zr;
        zr = nr; zi = ni;
        g_Z[(k + 1) * NL + l] = make_float2(zr, zi);
    }
}

// ---------------------------------------------------------------------------
// Kernel 3: output transform. U[k] = A*Re(z_k), V[k] = A*Im(z_k).
// ---------------------------------------------------------------------------
__global__ void __launch_bounds__(512, 1)
transform_kernel(float* __restrict__ out)
{
    __shared__ float  As[NL * NL];
    __shared__ float2 Zs[16 * NL];

    const int tid = threadIdx.x;
    for (int i = tid; i < NL * NL; i += 512) As[i] = g_A[i];

    const int kbase = blockIdx.x * 16;
    for (int i = tid; i < 16 * NL; i += 512) {
        int kk = i >> 5, li = i & 31;
        int k = kbase + kk;
        Zs[i] = (k >= 1 && k < NF) ? g_Z[k * NL + li] : make_float2(0.0f, 0.0f);
    }
    __syncthreads();

    const int kk = tid >> 5, r = tid & 31;
    const int k  = kbase + kk;
    if (k >= NF) return;

    const u64* zv = reinterpret_cast<const u64*>(&Zs[kk * NL]);
    u64 acc = 0ull;
    #pragma unroll
    for (int li = 0; li < NL; ++li) {
        float a = As[li * NL + r];
        ffma2(acc, pk2(a, a), zv[li]);
    }
    float u, v;
    upk2(u, v, acc);
    out[k * NL + r]           = u;
    out[NF * NL + k * NL + r] = v;
}

extern "C" void kernel_launch(void* const* d_in, const int* in_sizes, int n_in,
                              void* d_out, int out_size)
{
    const float* pk  = (const float*)d_in[0];
    const float* TAx = (const float*)d_in[1];
    const float* TAy = (const float*)d_in[2];
    const float* fc  = (const float*)d_in[3];
    float* out = (float*)d_out;

    eigen_kernel    <<<NL, 32>>>(pk, fc);
    modal_kernel    <<<1, 1024>>>(TAx, TAy);
    transform_kernel<<<45, 512>>>(out);
}

// round 11
// speedup vs baseline: 2.5383x; 1.1224x over previous
#include <cuda_runtime.h>

#define NL     32
#define NF     720
#define NSUB   60
#define DTF    60.0f
#define SCALE  256.0f
#define CL     23
#define NCH    32          // 31 full chunks of 23 + last of 6 (31*23+6 = 719)

typedef unsigned long long u64;
#define FULL 0xffffffffu

// Persistent scratch
__device__ float  g_A  [NL * NL];   // A[l*32+r] = Q[r][l] / d_r   (w = A z)
__device__ float2 g_Lam[NL];
__device__ float2 g_G0 [NL];
__device__ float2 g_G1 [NL];
__device__ float2 g_Z  [NF * NL];

// ---- packed f32x2 helpers ---------------------------------------------------
__device__ __forceinline__ u64 pk2(float lo, float hi) {
    u64 r; asm("mov.b64 %0, {%1, %2};" : "=l"(r) : "f"(lo), "f"(hi)); return r;
}
__device__ __forceinline__ void upk2(float& lo, float& hi, u64 v) {
    asm("mov.b64 {%0, %1}, %2;" : "=f"(lo), "=f"(hi) : "l"(v));
}
__device__ __forceinline__ void ffma2(u64& d, u64 a, u64 b) {
    asm("fma.rn.f32x2 %0, %1, %2, %3;" : "=l"(d) : "l"(a), "l"(b), "l"(d));
}

__device__ __forceinline__ float frcpa(float x) {   // raw MUFU rcp (approx)
    float r; asm("rcp.approx.f32 %0, %1;" : "=f"(r) : "f"(x)); return r;
}

// Sturm count: # eigenvalues of scaled symmetric tridiag < x
__device__ __forceinline__ int sturm_count(float x,
                                           const float* __restrict__ ch,
                                           const float* __restrict__ s2h)
{
    float p0 = 1.0f;
    float p1 = ch[0] - x;
    bool  s1 = (p1 < 0.0f) || (p1 == 0.0f);
    int   cnt = s1 ? 1 : 0;
    #pragma unroll
    for (int r = 1; r < NL; ++r) {
        float p2 = fmaf(ch[r] - x, p1, -s2h[r] * p0);
        bool sg = (p2 < 0.0f);
        if (p2 == 0.0f) sg = !s1;
        cnt += (sg != s1) ? 1 : 0;
        float ap = fabsf(p2);
        float sc = 1.0f;
        if (ap > 1e18f) sc = 1e-18f;
        else if (ap < 1e-18f) sc = 1e18f;
        p0 = p1 * sc;
        p1 = p2 * sc;
        s1 = sg;
    }
    return cnt;
}

__device__ __forceinline__ void cdmul(double& zr, double& zi, double ar, double ai) {
    double tr = zr * ar - zi * ai;
    zi = zr * ai + zi * ar;
    zr = tr;
}

// ---------------------------------------------------------------------------
// Kernel 1: eigen solve. 32 blocks x 1 warp.
// Bisection (lane-parallel); then DIVERGENT OVERLAP: lane 31 runs the Thomas
// inverse iteration while lanes 0..30 run the fp64 constants tail — the two
// are data-independent, ITS interleaves their issue.
// ---------------------------------------------------------------------------
__global__ void __launch_bounds__(32, 1)
eigen_kernel(const float* __restrict__ pk, const float* __restrict__ fc)
{
    __shared__ float ch [NL];
    __shared__ float sh [NL];       // off-diag connecting (l-1, l); sh[0]=0
    __shared__ float s2h[NL];
    __shared__ float vsm[NL];

    const int lane = threadIdx.x;
    const int l    = blockIdx.x;

    const float kin  = expf(pk[2 * lane]);
    const float kout = expf(pk[2 * lane + 1]);
    const float fc0  = fc[0];

    // symmetrizer: dinv_r = exp(-sum_{j<=r} 0.5*(pk[2j-1]-pk[2j]))
    float t = (lane > 0) ? 0.5f * (pk[2 * lane - 1] - pk[2 * lane]) : 0.0f;
    #pragma unroll
    for (int o = 1; o < 32; o <<= 1) {
        float u = __shfl_up_sync(FULL, t, o);
        if (lane >= o) t += u;
    }
    const float dinv = expf(-t);

    // scaled symmetric tridiagonal
    const float c = -DTF * (((lane > 0) ? kin : 0.0f) + kout) * SCALE;
    const float s = (lane > 0)
        ? DTF * expf(0.5f * (pk[2 * lane] + pk[2 * lane - 1])) * SCALE
        : 0.0f;
    ch[lane]  = c;
    sh[lane]  = s;
    s2h[lane] = s * s;
    const float s_up = __shfl_down_sync(FULL, s, 1);
    const float offp = (lane < NL - 1) ? s_up : 0.0f;
    __syncwarp();

    // Gershgorin interval
    float rad = s + offp;
    float lo  = c - rad, hi = c + rad;
    #pragma unroll
    for (int o = 16; o > 0; o >>= 1) {
        lo = fminf(lo, __shfl_xor_sync(FULL, lo, o));
        hi = fmaxf(hi, __shfl_xor_sync(FULL, hi, o));
    }
    float width = hi - lo;
    float a_ = lo - 1e-6f * (fabsf(width) + 1.0f);
    float b_ = hi + 1e-6f * (fabsf(width) + 1.0f);

    // 32-point parallel bisection, 5 rounds (interval /33 per round)
    for (int round = 0; round < 5; ++round) {
        float x = a_ + (b_ - a_) * (float)(lane + 1) * (1.0f / 33.0f);
        int cnt = sturm_count(x, ch, s2h);
        unsigned mask = __ballot_sync(FULL, cnt <= l);
        if (mask) {
            int j = 31 - __clz((int)mask);
            float na = __shfl_sync(FULL, x, j);
            float nb = (j < 31) ? __shfl_sync(FULL, x, j + 1) : b_;
            a_ = na; b_ = nb;
        } else {
            b_ = __shfl_sync(FULL, x, 0);
        }
    }
    const float xhat = 0.5f * (a_ + b_);

    // ---- divergent overlap: Thomas (lane 31)  ||  fp64 tail (lanes 0..30) ----
    double g0r = 0.0, g0i = 0.0, g1r = 0.0, g1i = 0.0;
    double Lr  = 0.0, Li  = 0.0;

    if (lane == 31) {
        // Thomas inverse iteration, all-register, rcp.approx + branchless clamp
        float vb[NL];
        #pragma unroll
        for (int r = 0; r < NL; ++r) vb[r] = 1.0f;

        #pragma unroll
        for (int it = 0; it < 3; ++it) {
            float rp[NL], wk[NL];
            float dd = ch[0] - xhat;
            dd = copysignf(fmaxf(fabsf(dd), 1e-12f), dd);
            rp[0] = frcpa(dd);
            wk[0] = vb[0];
            #pragma unroll
            for (int r = 1; r < NL; ++r) {
                float sv = sh[r];
                float m  = sv * rp[r - 1];
                dd = (ch[r] - xhat) - m * sv;
                dd = copysignf(fmaxf(fabsf(dd), 1e-12f), dd);
                rp[r] = frcpa(dd);
                wk[r] = vb[r] - m * wk[r - 1];
            }
            wk[NL - 1] = wk[NL - 1] * rp[NL - 1];
            #pragma unroll
            for (int r = NL - 2; r >= 0; --r)
                wk[r] = (wk[r] - sh[r + 1] * wk[r + 1]) * rp[r];

            float n2 = 0.0f;
            #pragma unroll
            for (int r = 0; r < NL; ++r) n2 += wk[r] * wk[r];
            float inv = rsqrtf(n2);
            #pragma unroll
            for (int r = 0; r < NL; ++r) vb[r] = wk[r] * inv;
        }
        #pragma unroll
        for (int r = 0; r < NL; ++r) vsm[r] = vb[r];
    } else {
        // fp64 constants tail: terms t1 = lane, t2 = lane + 31 (t2 < 60)
        const double mu = (double)xhat / (double)SCALE;
        const double br = 1.0 + mu;
        const double bi = -(double)DTF * (double)fc0;

        double sqr_r[6], sqr_i[6];
        sqr_r[0] = br; sqr_i[0] = bi;
        #pragma unroll
        for (int k = 1; k < 6; ++k) {
            double rr = sqr_r[k-1], ii = sqr_i[k-1];
            sqr_r[k] = rr * rr - ii * ii;
            sqr_i[k] = 2.0 * rr * ii;
        }

        const int e1 = 59 - lane;        // power for t1
        const int e2 = 28 - lane;        // power for t2 = lane+31 (valid if >= 0)
        double p1r = 1.0, p1i = 0.0, p2r = 1.0, p2i = 0.0;
        #pragma unroll
        for (int k = 0; k < 6; ++k) {
            if (e1 & (1 << k)) cdmul(p1r, p1i, sqr_r[k], sqr_i[k]);
            if (e2 >= 0 && (e2 & (1 << k))) cdmul(p2r, p2i, sqr_r[k], sqr_i[k]);
        }

        const double w2a = (double)lane * (1.0 / 60.0),        w1a = 1.0 - w2a;
        const double w2b = (double)(lane + 31) * (1.0 / 60.0), w1b = 1.0 - w2b;
        const bool   hb  = (e2 >= 0);
        g0r = w1a * p1r + (hb ? w1b * p2r : 0.0);
        g0i = w1a * p1i + (hb ? w1b * p2i : 0.0);
        g1r = w2a * p1r + (hb ? w2b * p2r : 0.0);
        g1i = w2a * p1i + (hb ? w2b * p2i : 0.0);

        // Lambda = beta^60 = beta^32 * beta^16 * beta^8 * beta^4
        Lr = sqr_r[5]; Li = sqr_i[5];
        cdmul(Lr, Li, sqr_r[4], sqr_i[4]);
        cdmul(Lr, Li, sqr_r[3], sqr_i[3]);
        cdmul(Lr, Li, sqr_r[2], sqr_i[2]);
    }
    __syncwarp();

    // reductions across the full warp (lane 31 contributes zeros)
    #pragma unroll
    for (int o = 16; o > 0; o >>= 1) {
        g0r += __shfl_xor_sync(FULL, g0r, o);
        g0i += __shfl_xor_sync(FULL, g0i, o);
        g1r += __shfl_xor_sync(FULL, g1r, o);
        g1i += __shfl_xor_sync(FULL, g1i, o);
    }

    const float v = vsm[lane];
    g_A[l * NL + lane] = v * dinv;

    if (lane == 0) {
        const double sc = (double)DTF * (double)expf(pk[0]) * (double)vsm[0];
        g_Lam[l] = make_float2((float)Lr, (float)Li);
        g_G0[l]  = make_float2((float)(sc * g0r), (float)(sc * g0i));
        g_G1[l]  = make_float2((float)(sc * g1r), (float)(sc * g1i));
    }
}

__device__ __forceinline__ float2 cmulf(float2 a, float2 b) {
    return make_float2(a.x * b.x - a.y * b.y, a.x * b.y + a.y * b.x);
}

// ---------------------------------------------------------------------------
// Kernel 2: modal evolution. ONE block, 32 warps. Warp c = chunk c, lane = mode.
// ---------------------------------------------------------------------------
__global__ void __launch_bounds__(1024, 1)
modal_kernel(const float* __restrict__ TAx, const float* __restrict__ TAy)
{
    __shared__ float2 zloc[NCH][NL];
    __shared__ float2 carr[NCH][NL];

    const int l = threadIdx.x & 31;
    const int c = threadIdx.x >> 5;

    const float2 L  = g_Lam[l];
    const float2 G0 = g_G0[l];
    const float2 G1 = g_G1[l];

    const int k0  = c * CL;
    const int len = min(CL, (NF - 1) - k0);

    float zr = 0.0f, zi = 0.0f;
    for (int m = 0; m < len; ++m) {
        const int k = k0 + m;
        float txa = TAx[k],     tya = TAy[k];
        float txb = TAx[k + 1], tyb = TAy[k + 1];
        float fr = txa * G0.x - tya * G0.y + txb * G1.x - tyb * G1.y;
        float fi = txa * G0.y + tya * G0.x + txb * G1.y + tyb * G1.x;
        float nr = fr + L.x * zr - L.y * zi;
        float ni = fi + L.x * zi + L.y * zr;
        zr = nr; zi = ni;
    }
    zloc[c][l] = make_float2(zr, zi);
    __syncthreads();

    if (c == 0) {
        float2 base = L, pw = make_float2(1.0f, 0.0f);
        int e = CL;
        while (e) { if (e & 1) pw = cmulf(pw, base); base = cmulf(base, base); e >>= 1; }

        float kr = 0.0f, ki = 0.0f;
        carr[0][l] = make_float2(0.0f, 0.0f);
        for (int cc = 0; cc < NCH - 1; ++cc) {
            float2 sv = zloc[cc][l];
            float nr = pw.x * kr - pw.y * ki + sv.x;
            float ni = pw.x * ki + pw.y * kr + sv.y;
            kr = nr; ki = ni;
            carr[cc + 1][l] = make_float2(kr, ki);
        }
    }
    __syncthreads();

    float2 K = carr[c][l];
    zr = K.x; zi = K.y;
    for (int m = 0; m < len; ++m) {
        const int k = k0 + m;
        float txa = TAx[k],     tya = TAy[k];
        float txb = TAx[k + 1], tyb = TAy[k + 1];
        float fr = txa * G0.x - tya * G0.y + txb * G1.x - tyb * G1.y;
        float fi = txa * G0.y + tya * G0.x + txb * G1.y + tyb * G1.x;
        float nr = fr + L.x * zr - L.y * zi;
        float ni = fi + L.x * zi + L.y * zr;
        zr = nr; zi = ni;
        g_Z[(k + 1) * NL + l] = make_float2(zr, zi);
    }
}

// ---------------------------------------------------------------------------
// Kernel 3: output transform. U[k] = A*Re(z_k), V[k] = A*Im(z_k).
// ---------------------------------------------------------------------------
__global__ void __launch_bounds__(512, 1)
transform_kernel(float* __restrict__ out)
{
    __shared__ float  As[NL * NL];
    __shared__ float2 Zs[16 * NL];

    const int tid = threadIdx.x;
    for (int i = tid; i < NL * NL; i += 512) As[i] = g_A[i];

    const int kbase = blockIdx.x * 16;
    for (int i = tid; i < 16 * NL; i += 512) {
        int kk = i >> 5, li = i & 31;
        int k = kbase + kk;
        Zs[i] = (k >= 1 && k < NF) ? g_Z[k * NL + li] : make_float2(0.0f, 0.0f);
    }
    __syncthreads();

    const int kk = tid >> 5, r = tid & 31;
    const int k  = kbase + kk;
    if (k >= NF) return;

    const u64* zv = reinterpret_cast<const u64*>(&Zs[kk * NL]);
    u64 acc = 0ull;
    #pragma unroll
    for (int li = 0; li < NL; ++li) {
        float a = As[li * NL + r];
        ffma2(acc, pk2(a, a), zv[li]);
    }
    float u, v;
    upk2(u, v, acc);
    out[k * NL + r]           = u;
    out[NF * NL + k * NL + r] = v;
}

extern "C" void kernel_launch(void* const* d_in, const int* in_sizes, int n_in,
                              void* d_out, int out_size)
{
    const float* pk  = (const float*)d_in[0];
    const float* TAx = (const float*)d_in[1];
    const float* TAy = (const float*)d_in[2];
    const float* fc  = (const float*)d_in[3];
    float* out = (float*)d_out;

    eigen_kernel    <<<NL, 32>>>(pk, fc);
    modal_kernel    <<<1, 1024>>>(TAx, TAy);
    transform_kernel<<<45, 512>>>(out);
}